// round 1
// baseline (speedup 1.0000x reference)
#include <cuda_runtime.h>
#include <math.h>

#define B 8
#define SEQ 2048
#define HID 512
#define HD 64
#define CHUNKSZ 256

// ---------------- scratch (device globals; no allocation allowed) ----------------
__device__ float gQ[B * SEQ * HD];
__device__ float gK[B * SEQ * HD];
__device__ float gV[B * SEQ * HD];
// xPos tables: per (t, pair m): cos_f / sin_f for Q (upscale) and K (downscale)
__device__ float tQc[SEQ * 32], tQs[SEQ * 32], tKc[SEQ * 32], tKs[SEQ * 32];

// ---------------- kernel 0: xPos sin/cos/scale table ----------------
__global__ void table_kernel() {
    int idx = blockIdx.x * blockDim.x + threadIdx.x;
    if (idx >= SEQ * 32) return;
    int t = idx >> 5;
    int m = idx & 31;
    // scale_vec[m] = (2m + 0.4*hd) / (1.4*hd), power = t / 512
    float sv = (2.0f * (float)m + 0.4f * (float)HD) / (1.4f * (float)HD);
    float s = powf(sv, (float)t / 512.0f);
    // inv_freq[m] = 10000^(-m/32); match reference's fp32 angle rounding
    float invf = 1.0f / powf(10000.0f, (float)m / 32.0f);
    float ang = (float)t * invf;
    float sn, cs;
    sincosf(ang, &sn, &cs);
    tQc[idx] = cs * s;
    tQs[idx] = sn * s;
    tKc[idx] = cs / s;
    tKs[idx] = sn / s;
}

// ---------------- kernel 1: fused QKV projection + xPos ----------------
// grid (32 t-tiles, 8 b), block 256. Output tile per CTA: 64 rows x 192 cols (Q|K|V).
__global__ __launch_bounds__(256) void proj_kernel(
    const float* __restrict__ X,
    const float* __restrict__ WQ,
    const float* __restrict__ WK,
    const float* __restrict__ WV) {
    __shared__ float Xs[64][36];    // 64 rows x 32 k (+4 pad, 16B-aligned stride)
    __shared__ float Wt[192][36];   // transposed W tile: [col][k]

    int b = blockIdx.y, tt = blockIdx.x;
    int tid = threadIdx.x;
    int ty = tid >> 4, tx = tid & 15;

    const float* Xb = X + ((size_t)b * SEQ + (size_t)tt * 64) * HID;

    float acc[4][12];
#pragma unroll
    for (int i = 0; i < 4; i++)
#pragma unroll
        for (int j = 0; j < 12; j++) acc[i][j] = 0.0f;

    for (int h0 = 0; h0 < HID; h0 += 32) {
        __syncthreads();
        // load X tile 64x32 (coalesced)
#pragma unroll
        for (int i = 0; i < 8; i++) {
            int e = tid + i * 256;
            int r = e >> 5, c = e & 31;
            Xs[r][c] = Xb[r * HID + h0 + c];
        }
        // load W tiles transposed: cols 0..63 Q, 64..127 K, 128..191 V
#pragma unroll
        for (int i = 0; i < 24; i++) {
            int e = tid + i * 256;     // 6144 = 32k x 192c
            int k = e / 192, cf = e % 192;
            const float* W = (cf < 64) ? WQ : ((cf < 128) ? WK : WV);
            int d = cf & 63;
            Wt[cf][k] = W[(h0 + k) * HD + d];
        }
        __syncthreads();

#pragma unroll
        for (int k4 = 0; k4 < 32; k4 += 4) {
            float4 a[4];
#pragma unroll
            for (int rr = 0; rr < 4; rr++)
                a[rr] = *(const float4*)&Xs[ty * 4 + rr][k4];
            float4 bb[12];
#pragma unroll
            for (int cc = 0; cc < 12; cc++)
                bb[cc] = *(const float4*)&Wt[tx * 12 + cc][k4];
#pragma unroll
            for (int rr = 0; rr < 4; rr++)
#pragma unroll
                for (int cc = 0; cc < 12; cc++) {
                    acc[rr][cc] += a[rr].x * bb[cc].x;
                    acc[rr][cc] += a[rr].y * bb[cc].y;
                    acc[rr][cc] += a[rr].z * bb[cc].z;
                    acc[rr][cc] += a[rr].w * bb[cc].w;
                }
        }
    }

    // epilogue: xPos rotary on Q/K pairs, passthrough V. Thread owns 12 consecutive
    // cols starting at tx*12 (even) so rotary pairs never straddle threads/regions.
#pragma unroll
    for (int rr = 0; rr < 4; rr++) {
        int t = tt * 64 + ty * 4 + rr;
        size_t rowbase = ((size_t)b * SEQ + t) * HD;
#pragma unroll
        for (int p = 0; p < 6; p++) {
            int c0 = tx * 12 + 2 * p;
            float x0 = acc[rr][2 * p];
            float x1 = acc[rr][2 * p + 1];
            if (c0 < 64) {
                int m = c0 >> 1;
                float cs = tQc[t * 32 + m], sn = tQs[t * 32 + m];
                gQ[rowbase + c0]     = x0 * cs - x1 * sn;
                gQ[rowbase + c0 + 1] = x1 * cs + x0 * sn;
            } else if (c0 < 128) {
                int d = c0 - 64;
                int m = d >> 1;
                float cs = tKc[t * 32 + m], sn = tKs[t * 32 + m];
                gK[rowbase + d]     = x0 * cs - x1 * sn;
                gK[rowbase + d + 1] = x1 * cs + x0 * sn;
            } else {
                int d = c0 - 128;
                gV[rowbase + d]     = x0;
                gV[rowbase + d + 1] = x1;
            }
        }
    }
}

// ---------------- kernel 2: decay-masked attention ----------------
// grid (32 q-tiles, 8 b), block 256. Q tile 64x64; loop over K/V tiles of 64 rows.
// Allowed j: j < (chunk+1)*256 (full diagonal chunk), truncated 512 positions back
// (gamma^512 ~ 8.7e-8, negligible vs 1e-3 tolerance).
#define SMSTRIDE 68
__global__ __launch_bounds__(256) void attn_kernel(float* __restrict__ out) {
    extern __shared__ float sm[];
    float* Qs = sm;
    float* Ks = Qs + 64 * SMSTRIDE;
    float* Vs = Ks + 64 * SMSTRIDE;
    float* Ss = Vs + 64 * SMSTRIDE;

    int qt = blockIdx.x, b = blockIdx.y;
    int tid = threadIdx.x;
    int ty = tid >> 4, tx = tid & 15;
    int q0 = qt * 64;

    const float* Qg = gQ + ((size_t)b * SEQ + q0) * HD;
#pragma unroll
    for (int i = 0; i < 4; i++) {
        int e = tid + i * 256;        // 1024 float4s
        int r = e >> 4, c4 = e & 15;
        *(float4*)&Qs[r * SMSTRIDE + c4 * 4] = *(const float4*)&Qg[r * HD + c4 * 4];
    }

    float4 oacc[4];
#pragma unroll
    for (int rr = 0; rr < 4; rr++) oacc[rr] = make_float4(0.f, 0.f, 0.f, 0.f);

    int chunk = qt >> 2;
    int kt_end = (chunk + 1) * 4;
    int kt_start = qt - 8;
    if (kt_start < 0) kt_start = 0;
    const float lg = log2f(0.96875f);  // negative constant, folded

    for (int kt = kt_start; kt < kt_end; kt++) {
        __syncthreads();  // previous iter done reading Ks/Vs/Ss
        const float* Kg = gK + ((size_t)b * SEQ + kt * 64) * HD;
        const float* Vg = gV + ((size_t)b * SEQ + kt * 64) * HD;
#pragma unroll
        for (int i = 0; i < 4; i++) {
            int e = tid + i * 256;
            int r = e >> 4, c4 = e & 15;
            *(float4*)&Ks[r * SMSTRIDE + c4 * 4] = *(const float4*)&Kg[r * HD + c4 * 4];
            *(float4*)&Vs[r * SMSTRIDE + c4 * 4] = *(const float4*)&Vg[r * HD + c4 * 4];
        }
        __syncthreads();

        // S = Q K^T (thread tile 4 rows x 4 cols)
        float s[4][4];
#pragma unroll
        for (int rr = 0; rr < 4; rr++)
#pragma unroll
            for (int jj = 0; jj < 4; jj++) s[rr][jj] = 0.0f;

#pragma unroll
        for (int d4 = 0; d4 < 64; d4 += 4) {
            float4 a[4];
#pragma unroll
            for (int rr = 0; rr < 4; rr++)
                a[rr] = *(const float4*)&Qs[(ty * 4 + rr) * SMSTRIDE + d4];
            float4 bv[4];
#pragma unroll
            for (int jj = 0; jj < 4; jj++)
                bv[jj] = *(const float4*)&Ks[(tx * 4 + jj) * SMSTRIDE + d4];
#pragma unroll
            for (int rr = 0; rr < 4; rr++)
#pragma unroll
                for (int jj = 0; jj < 4; jj++) {
                    s[rr][jj] += a[rr].x * bv[jj].x;
                    s[rr][jj] += a[rr].y * bv[jj].y;
                    s[rr][jj] += a[rr].z * bv[jj].z;
                    s[rr][jj] += a[rr].w * bv[jj].w;
                }
        }

        // decay mask gamma^|i-j| and stage S in smem
#pragma unroll
        for (int rr = 0; rr < 4; rr++) {
            int i = q0 + ty * 4 + rr;
#pragma unroll
            for (int jj = 0; jj < 4; jj++) {
                int jgl = kt * 64 + tx * 4 + jj;
                float dist = fabsf((float)(i - jgl));
                float dec = exp2f(lg * dist);
                Ss[(ty * 4 + rr) * SMSTRIDE + tx * 4 + jj] = s[rr][jj] * dec;
            }
        }
        __syncthreads();

        // out += S @ V   (thread tile 4 rows x float4 cols at tx*4)
#pragma unroll 4
        for (int j = 0; j < 64; j++) {
            float4 v = *(const float4*)&Vs[j * SMSTRIDE + tx * 4];
#pragma unroll
            for (int rr = 0; rr < 4; rr++) {
                float sv = Ss[(ty * 4 + rr) * SMSTRIDE + j];
                oacc[rr].x += sv * v.x;
                oacc[rr].y += sv * v.y;
                oacc[rr].z += sv * v.z;
                oacc[rr].w += sv * v.w;
            }
        }
    }

    float* O = out + ((size_t)b * SEQ + q0) * HD;
#pragma unroll
    for (int rr = 0; rr < 4; rr++)
        *(float4*)&O[(ty * 4 + rr) * HD + tx * 4] = oacc[rr];
}

// ---------------- launch ----------------
extern "C" void kernel_launch(void* const* d_in, const int* in_sizes, int n_in,
                              void* d_out, int out_size) {
    const float* X  = (const float*)d_in[0];
    const float* WQ = (const float*)d_in[1];
    const float* WK = (const float*)d_in[2];
    const float* WV = (const float*)d_in[3];
    float* out = (float*)d_out;

    table_kernel<<<(SEQ * 32 + 255) / 256, 256>>>();
    proj_kernel<<<dim3(32, B), 256>>>(X, WQ, WK, WV);

    int smem = 4 * 64 * SMSTRIDE * 4;  // 69632 B
    cudaFuncSetAttribute(attn_kernel, cudaFuncAttributeMaxDynamicSharedMemorySize, smem);
    attn_kernel<<<dim3(32, B), 256, smem>>>(out);
}

// round 3
// speedup vs baseline: 4.0279x; 4.0279x over previous
#include <cuda_runtime.h>
#include <cuda_bf16.h>
#include <math.h>
#include <stdint.h>

#define B 8
#define SEQ 2048
#define HID 512
#define HD 64

// ---------------- scratch (device globals; no allocation allowed) ----------------
__device__ uint16_t gQh[B * SEQ * HD], gQl[B * SEQ * HD];
__device__ uint16_t gKh[B * SEQ * HD], gKl[B * SEQ * HD];
__device__ float gV[B * SEQ * HD];
__device__ float tQc[SEQ * 32], tQs[SEQ * 32], tKc[SEQ * 32], tKs[SEQ * 32];
__device__ float tDec[4096];   // gamma^|d|, index d+2048

// ---------------- helpers ----------------
__device__ __forceinline__ void mma_bf16(float* d, const uint32_t* a, const uint32_t* b) {
    asm volatile(
        "mma.sync.aligned.m16n8k16.row.col.f32.bf16.bf16.f32 "
        "{%0,%1,%2,%3}, {%4,%5,%6,%7}, {%8,%9}, {%0,%1,%2,%3};"
        : "+f"(d[0]), "+f"(d[1]), "+f"(d[2]), "+f"(d[3])
        : "r"(a[0]), "r"(a[1]), "r"(a[2]), "r"(a[3]), "r"(b[0]), "r"(b[1]));
}
__device__ __forceinline__ uint32_t cvt_hi(float x0, float x1, float& r0, float& r1) {
    __nv_bfloat16 h0 = __float2bfloat16(x0), h1 = __float2bfloat16(x1);
    r0 = x0 - __bfloat162float(h0);
    r1 = x1 - __bfloat162float(h1);
    return ((uint32_t)__bfloat16_as_ushort(h1) << 16) | (uint32_t)__bfloat16_as_ushort(h0);
}
__device__ __forceinline__ uint32_t pack_bf(float x0, float x1) {
    __nv_bfloat16 h0 = __float2bfloat16(x0), h1 = __float2bfloat16(x1);
    return ((uint32_t)__bfloat16_as_ushort(h1) << 16) | (uint32_t)__bfloat16_as_ushort(h0);
}

// ---------------- kernel 0: tables ----------------
__global__ void table_kernel() {
    int idx = blockIdx.x * blockDim.x + threadIdx.x;
    if (idx < 4096) {
        float d = fabsf((float)(idx - 2048));
        tDec[idx] = exp2f(log2f(0.96875f) * d);
    }
    if (idx >= SEQ * 32) return;
    int t = idx >> 5;
    int m = idx & 31;
    float sv = (2.0f * (float)m + 0.4f * (float)HD) / (1.4f * (float)HD);
    float s = powf(sv, (float)t / 512.0f);
    float invf = 1.0f / powf(10000.0f, (float)m / 32.0f);
    float ang = (float)t * invf;
    float sn, cs;
    sincosf(ang, &sn, &cs);
    tQc[idx] = cs * s;
    tQs[idx] = sn * s;
    tKc[idx] = cs / s;
    tKs[idx] = sn / s;
}

// ---------------- kernel 1: QKV projection via HMMA + xPos ----------------
// 128 CTAs x 256 thr (8 warps 4x2). CTA tile 128x192, warp tile 32x96.
#define PSTR 72     // bf16 row stride (conflict-free fragment loads)
#define P_AH 0
#define P_AL 18432
#define P_BH 36864
#define P_BL 64512
#define P_TOTAL 92160

__global__ __launch_bounds__(256, 1) void proj_kernel(
    const float* __restrict__ X,
    const float* __restrict__ WQ,
    const float* __restrict__ WK,
    const float* __restrict__ WV) {
    extern __shared__ char sm[];
    uint16_t* Ah = (uint16_t*)(sm + P_AH);
    uint16_t* Al = (uint16_t*)(sm + P_AL);
    uint16_t* Bh = (uint16_t*)(sm + P_BH);
    uint16_t* Bl = (uint16_t*)(sm + P_BL);

    int tid = threadIdx.x;
    int wid = tid >> 5, lane = tid & 31;
    int wm = wid >> 1, wn = wid & 1;
    int g = lane >> 2, tc = lane & 3;

    const float* Xb = X + (size_t)blockIdx.x * 128 * HID;
    const float* Wp[3] = {WQ, WK, WV};

    float acc[2][12][4];
#pragma unroll
    for (int mt = 0; mt < 2; mt++)
#pragma unroll
        for (int nt = 0; nt < 12; nt++)
#pragma unroll
            for (int i = 0; i < 4; i++) acc[mt][nt][i] = 0.0f;

    for (int chunk = 0; chunk < 8; chunk++) {
        int k0 = chunk * 64;
        if (chunk) __syncthreads();
        // A tile: 128 rows x 32 k-pairs, coalesced float2 reads
#pragma unroll
        for (int it = 0; it < 16; it++) {
            int e = tid + it * 256;
            int r = e >> 5, p = e & 31;
            float2 v = *(const float2*)&Xb[r * HID + k0 + 2 * p];
            float l0, l1;
            uint32_t hi = cvt_hi(v.x, v.y, l0, l1);
            *(uint32_t*)&Ah[r * PSTR + 2 * p] = hi;
            *(uint32_t*)&Al[r * PSTR + 2 * p] = pack_bf(l0, l1);
        }
        // B tile: 192 n-rows (Q|K|V) x 32 k-pairs
#pragma unroll
        for (int it = 0; it < 24; it++) {
            int e = tid + it * 256;
            int d = e & 63;
            int rem = e >> 6;
            int region = rem >> 5;
            int kp = rem & 31;
            const float* W = Wp[region];
            float x0 = W[(k0 + 2 * kp) * HD + d];
            float x1 = W[(k0 + 2 * kp + 1) * HD + d];
            float l0, l1;
            uint32_t hi = cvt_hi(x0, x1, l0, l1);
            int nrow = region * 64 + d;
            *(uint32_t*)&Bh[nrow * PSTR + 2 * kp] = hi;
            *(uint32_t*)&Bl[nrow * PSTR + 2 * kp] = pack_bf(l0, l1);
        }
        __syncthreads();

#pragma unroll
        for (int ks = 0; ks < 4; ks++) {
            int kk = ks * 16;
            uint32_t ah[2][4], al[2][4];
#pragma unroll
            for (int mt = 0; mt < 2; mt++) {
                int r = wm * 32 + mt * 16;
                ah[mt][0] = *(uint32_t*)&Ah[(r + g) * PSTR + kk + 2 * tc];
                ah[mt][1] = *(uint32_t*)&Ah[(r + g + 8) * PSTR + kk + 2 * tc];
                ah[mt][2] = *(uint32_t*)&Ah[(r + g) * PSTR + kk + 8 + 2 * tc];
                ah[mt][3] = *(uint32_t*)&Ah[(r + g + 8) * PSTR + kk + 8 + 2 * tc];
                al[mt][0] = *(uint32_t*)&Al[(r + g) * PSTR + kk + 2 * tc];
                al[mt][1] = *(uint32_t*)&Al[(r + g + 8) * PSTR + kk + 2 * tc];
                al[mt][2] = *(uint32_t*)&Al[(r + g) * PSTR + kk + 8 + 2 * tc];
                al[mt][3] = *(uint32_t*)&Al[(r + g + 8) * PSTR + kk + 8 + 2 * tc];
            }
#pragma unroll
            for (int nt = 0; nt < 12; nt++) {
                int n = wn * 96 + nt * 8;
                uint32_t bh[2], bl[2];
                bh[0] = *(uint32_t*)&Bh[(n + g) * PSTR + kk + 2 * tc];
                bh[1] = *(uint32_t*)&Bh[(n + g) * PSTR + kk + 8 + 2 * tc];
                bl[0] = *(uint32_t*)&Bl[(n + g) * PSTR + kk + 2 * tc];
                bl[1] = *(uint32_t*)&Bl[(n + g) * PSTR + kk + 8 + 2 * tc];
#pragma unroll
                for (int mt = 0; mt < 2; mt++) {
                    mma_bf16(acc[mt][nt], ah[mt], bh);
                    mma_bf16(acc[mt][nt], ah[mt], bl);
                    mma_bf16(acc[mt][nt], al[mt], bh);
                }
            }
        }
    }

    // epilogue: rotary on Q/K col pairs, split hi/lo, store
#pragma unroll
    for (int mt = 0; mt < 2; mt++) {
#pragma unroll
        for (int half = 0; half < 2; half++) {
            int lrow = wm * 32 + mt * 16 + g + half * 8;
            int grow = blockIdx.x * 128 + lrow;
            int tpos = grow & (SEQ - 1);
#pragma unroll
            for (int nt = 0; nt < 12; nt++) {
                int c = wn * 96 + nt * 8 + 2 * tc;
                float v0 = acc[mt][nt][half * 2];
                float v1 = acc[mt][nt][half * 2 + 1];
                if (c < 64) {
                    int m = c >> 1;
                    float cs = tQc[tpos * 32 + m], sn = tQs[tpos * 32 + m];
                    float o0 = v0 * cs - v1 * sn;
                    float o1 = v1 * cs + v0 * sn;
                    float l0, l1;
                    uint32_t hi = cvt_hi(o0, o1, l0, l1);
                    ((uint32_t*)gQh)[grow * 32 + m] = hi;
                    ((uint32_t*)gQl)[grow * 32 + m] = pack_bf(l0, l1);
                } else if (c < 128) {
                    int m = (c - 64) >> 1;
                    float cs = tKc[tpos * 32 + m], sn = tKs[tpos * 32 + m];
                    float o0 = v0 * cs - v1 * sn;
                    float o1 = v1 * cs + v0 * sn;
                    float l0, l1;
                    uint32_t hi = cvt_hi(o0, o1, l0, l1);
                    ((uint32_t*)gKh)[grow * 32 + m] = hi;
                    ((uint32_t*)gKl)[grow * 32 + m] = pack_bf(l0, l1);
                } else {
                    *(float2*)&gV[(size_t)grow * HD + (c - 128)] = make_float2(v0, v1);
                }
            }
        }
    }
}

// ---------------- kernel 2: retention attention via HMMA ----------------
// grid (32 qt, 8 b) x 256 thr (8 warps 4x2). Warp tile 16x32 for both GEMMs.
#define ASTR 72
#define A_QH 0
#define A_QL 9216
#define A_KH 18432
#define A_KL 27648
#define A_VH 36864
#define A_VL 46080
#define A_SH 55296
#define A_SL 64512
#define A_TOTAL 73728

__global__ __launch_bounds__(256, 2) void attn_kernel(float* __restrict__ out) {
    extern __shared__ char sm[];
    uint16_t* Qh = (uint16_t*)(sm + A_QH);
    uint16_t* Ql = (uint16_t*)(sm + A_QL);
    uint16_t* Kh = (uint16_t*)(sm + A_KH);
    uint16_t* Kl = (uint16_t*)(sm + A_KL);
    uint16_t* Vh = (uint16_t*)(sm + A_VH);   // transposed [dim][tok]
    uint16_t* Vl = (uint16_t*)(sm + A_VL);
    uint16_t* Sh = (uint16_t*)(sm + A_SH);
    uint16_t* Sl = (uint16_t*)(sm + A_SL);

    int qt = blockIdx.x, b = blockIdx.y;
    int tid = threadIdx.x;
    int wid = tid >> 5, lane = tid & 31;
    int wm = wid >> 1, wn = wid & 1;
    int g = lane >> 2, tc = lane & 3;
    int q0 = qt * 64;
    int gb = b * SEQ + q0;

    // load Q tile (hi/lo) once
#pragma unroll
    for (int it = 0; it < 8; it++) {
        int e = tid + it * 256;
        int r = e >> 5, p = e & 31;
        *(uint32_t*)&Qh[r * ASTR + 2 * p] = ((const uint32_t*)gQh)[(gb + r) * 32 + p];
        *(uint32_t*)&Ql[r * ASTR + 2 * p] = ((const uint32_t*)gQl)[(gb + r) * 32 + p];
    }

    float oacc[4][4];
#pragma unroll
    for (int nt = 0; nt < 4; nt++)
#pragma unroll
        for (int i = 0; i < 4; i++) oacc[nt][i] = 0.0f;

    int chunk = qt >> 2;
    int kt_end = (chunk + 1) * 4;
    int kt_start = qt - 8;
    if (kt_start < 0) kt_start = 0;

    for (int kt = kt_start; kt < kt_end; kt++) {
        __syncthreads();
        int kb = b * SEQ + kt * 64;
        // K tile hi/lo
#pragma unroll
        for (int it = 0; it < 8; it++) {
            int e = tid + it * 256;
            int r = e >> 5, p = e & 31;
            *(uint32_t*)&Kh[r * ASTR + 2 * p] = ((const uint32_t*)gKh)[(kb + r) * 32 + p];
            *(uint32_t*)&Kl[r * ASTR + 2 * p] = ((const uint32_t*)gKl)[(kb + r) * 32 + p];
        }
        // V tile: read fp32 coalesced, convert+transpose into [dim][tok]
#pragma unroll
        for (int it = 0; it < 8; it++) {
            int e = tid + it * 256;
            int d = e & 63, jp = e >> 6;
            float f0 = gV[(size_t)(kb + 2 * jp) * HD + d];
            float f1 = gV[(size_t)(kb + 2 * jp + 1) * HD + d];
            float l0, l1;
            uint32_t hi = cvt_hi(f0, f1, l0, l1);
            *(uint32_t*)&Vh[d * ASTR + 2 * jp] = hi;
            *(uint32_t*)&Vl[d * ASTR + 2 * jp] = pack_bf(l0, l1);
        }
        __syncthreads();

        // ---- S = Q K^T (warp tile 16x32) ----
        float s[4][4];
#pragma unroll
        for (int nt = 0; nt < 4; nt++)
#pragma unroll
            for (int i = 0; i < 4; i++) s[nt][i] = 0.0f;
#pragma unroll
        for (int ks = 0; ks < 4; ks++) {
            int kk = ks * 16;
            uint32_t ah[4], al[4];
            int r = wm * 16;
            ah[0] = *(uint32_t*)&Qh[(r + g) * ASTR + kk + 2 * tc];
            ah[1] = *(uint32_t*)&Qh[(r + g + 8) * ASTR + kk + 2 * tc];
            ah[2] = *(uint32_t*)&Qh[(r + g) * ASTR + kk + 8 + 2 * tc];
            ah[3] = *(uint32_t*)&Qh[(r + g + 8) * ASTR + kk + 8 + 2 * tc];
            al[0] = *(uint32_t*)&Ql[(r + g) * ASTR + kk + 2 * tc];
            al[1] = *(uint32_t*)&Ql[(r + g + 8) * ASTR + kk + 2 * tc];
            al[2] = *(uint32_t*)&Ql[(r + g) * ASTR + kk + 8 + 2 * tc];
            al[3] = *(uint32_t*)&Ql[(r + g + 8) * ASTR + kk + 8 + 2 * tc];
#pragma unroll
            for (int nt = 0; nt < 4; nt++) {
                int n = wn * 32 + nt * 8;
                uint32_t bh[2], bl[2];
                bh[0] = *(uint32_t*)&Kh[(n + g) * ASTR + kk + 2 * tc];
                bh[1] = *(uint32_t*)&Kh[(n + g) * ASTR + kk + 8 + 2 * tc];
                bl[0] = *(uint32_t*)&Kl[(n + g) * ASTR + kk + 2 * tc];
                bl[1] = *(uint32_t*)&Kl[(n + g) * ASTR + kk + 8 + 2 * tc];
                mma_bf16(s[nt], ah, bh);
                mma_bf16(s[nt], ah, bl);
                mma_bf16(s[nt], al, bh);
            }
        }

        // ---- decay + split hi/lo into smem ----
        {
            int i0 = q0 + wm * 16 + g;
#pragma unroll
            for (int nt = 0; nt < 4; nt++) {
                int jg = kt * 64 + wn * 32 + nt * 8 + 2 * tc;
                float d00 = tDec[i0 - jg + 2048];
                float d01 = tDec[i0 - jg + 2047];
                float d10 = tDec[i0 + 8 - jg + 2048];
                float d11 = tDec[i0 + 8 - jg + 2047];
                float v0 = s[nt][0] * d00, v1 = s[nt][1] * d01;
                float v2 = s[nt][2] * d10, v3 = s[nt][3] * d11;
                int cl = wn * 32 + nt * 8 + 2 * tc;
                float l0, l1;
                uint32_t hi0 = cvt_hi(v0, v1, l0, l1);
                *(uint32_t*)&Sh[(wm * 16 + g) * ASTR + cl] = hi0;
                *(uint32_t*)&Sl[(wm * 16 + g) * ASTR + cl] = pack_bf(l0, l1);
                uint32_t hi1 = cvt_hi(v2, v3, l0, l1);
                *(uint32_t*)&Sh[(wm * 16 + g + 8) * ASTR + cl] = hi1;
                *(uint32_t*)&Sl[(wm * 16 + g + 8) * ASTR + cl] = pack_bf(l0, l1);
            }
        }
        __syncthreads();

        // ---- O += S V (A=S [i][j], B=Vt [dim][j]) ----
#pragma unroll
        for (int ks = 0; ks < 4; ks++) {
            int kk = ks * 16;
            uint32_t ah[4], al[4];
            int r = wm * 16;
            ah[0] = *(uint32_t*)&Sh[(r + g) * ASTR + kk + 2 * tc];
            ah[1] = *(uint32_t*)&Sh[(r + g + 8) * ASTR + kk + 2 * tc];
            ah[2] = *(uint32_t*)&Sh[(r + g) * ASTR + kk + 8 + 2 * tc];
            ah[3] = *(uint32_t*)&Sh[(r + g + 8) * ASTR + kk + 8 + 2 * tc];
            al[0] = *(uint32_t*)&Sl[(r + g) * ASTR + kk + 2 * tc];
            al[1] = *(uint32_t*)&Sl[(r + g + 8) * ASTR + kk + 2 * tc];
            al[2] = *(uint32_t*)&Sl[(r + g) * ASTR + kk + 8 + 2 * tc];
            al[3] = *(uint32_t*)&Sl[(r + g + 8) * ASTR + kk + 8 + 2 * tc];
#pragma unroll
            for (int nt = 0; nt < 4; nt++) {
                int n = wn * 32 + nt * 8;
                uint32_t bh[2], bl[2];
                bh[0] = *(uint32_t*)&Vh[(n + g) * ASTR + kk + 2 * tc];
                bh[1] = *(uint32_t*)&Vh[(n + g) * ASTR + kk + 8 + 2 * tc];
                bl[0] = *(uint32_t*)&Vl[(n + g) * ASTR + kk + 2 * tc];
                bl[1] = *(uint32_t*)&Vl[(n + g) * ASTR + kk + 8 + 2 * tc];
                mma_bf16(oacc[nt], ah, bh);
                mma_bf16(oacc[nt], ah, bl);
                mma_bf16(oacc[nt], al, bh);
            }
        }
    }

    // store O
#pragma unroll
    for (int nt = 0; nt < 4; nt++) {
        int c = wn * 32 + nt * 8 + 2 * tc;
        int r0 = wm * 16 + g;
        *(float2*)&out[(size_t)(gb + r0) * HD + c] = make_float2(oacc[nt][0], oacc[nt][1]);
        *(float2*)&out[(size_t)(gb + r0 + 8) * HD + c] = make_float2(oacc[nt][2], oacc[nt][3]);
    }
}

// ---------------- launch ----------------
extern "C" void kernel_launch(void* const* d_in, const int* in_sizes, int n_in,
                              void* d_out, int out_size) {
    const float* X  = (const float*)d_in[0];
    const float* WQ = (const float*)d_in[1];
    const float* WK = (const float*)d_in[2];
    const float* WV = (const float*)d_in[3];
    float* out = (float*)d_out;

    table_kernel<<<(SEQ * 32 + 255) / 256, 256>>>();

    cudaFuncSetAttribute(proj_kernel, cudaFuncAttributeMaxDynamicSharedMemorySize, P_TOTAL);
    proj_kernel<<<128, 256, P_TOTAL>>>(X, WQ, WK, WV);

    cudaFuncSetAttribute(attn_kernel, cudaFuncAttributeMaxDynamicSharedMemorySize, A_TOTAL);
    attn_kernel<<<dim3(32, B), 256, A_TOTAL>>>(out);
}

// round 4
// speedup vs baseline: 4.9697x; 1.2338x over previous
#include <cuda_runtime.h>
#include <cuda_bf16.h>
#include <math.h>
#include <stdint.h>

#define B 8
#define SEQ 2048
#define HID 512
#define HD 64

// ---------------- scratch (device globals; no allocation allowed) ----------------
__device__ uint16_t gQh[B * SEQ * HD], gQl[B * SEQ * HD];
__device__ uint16_t gKh[B * SEQ * HD], gKl[B * SEQ * HD];
__device__ uint16_t gVh[B * SEQ * HD], gVl[B * SEQ * HD];
__device__ uint16_t gWh[192 * HID], gWl[192 * HID];   // [region*64+d][k]
__device__ float tQc[SEQ * 32], tQs[SEQ * 32], tKc[SEQ * 32], tKs[SEQ * 32];
__device__ float tDec[4096];   // gamma^|d|, index d+2048

// ---------------- helpers ----------------
__device__ __forceinline__ void mma_bf16(float* d, const uint32_t* a, const uint32_t* b) {
    asm volatile(
        "mma.sync.aligned.m16n8k16.row.col.f32.bf16.bf16.f32 "
        "{%0,%1,%2,%3}, {%4,%5,%6,%7}, {%8,%9}, {%0,%1,%2,%3};"
        : "+f"(d[0]), "+f"(d[1]), "+f"(d[2]), "+f"(d[3])
        : "r"(a[0]), "r"(a[1]), "r"(a[2]), "r"(a[3]), "r"(b[0]), "r"(b[1]));
}
#define LDM_X4(R, a) \
    asm volatile("ldmatrix.sync.aligned.m8n8.x4.shared.b16 {%0,%1,%2,%3}, [%4];" \
                 : "=r"((R)[0]), "=r"((R)[1]), "=r"((R)[2]), "=r"((R)[3]) : "r"(a))
#define LDM_X4T(R, a) \
    asm volatile("ldmatrix.sync.aligned.m8n8.x4.trans.shared.b16 {%0,%1,%2,%3}, [%4];" \
                 : "=r"((R)[0]), "=r"((R)[1]), "=r"((R)[2]), "=r"((R)[3]) : "r"(a))
__device__ __forceinline__ uint32_t smem_u32(const void* p) {
    uint32_t a;
    asm("{ .reg .u64 t; cvta.to.shared.u64 t, %1; cvt.u32.u64 %0, t; }" : "=r"(a) : "l"(p));
    return a;
}
__device__ __forceinline__ uint32_t cvt_hi(float x0, float x1, float& r0, float& r1) {
    __nv_bfloat16 h0 = __float2bfloat16(x0), h1 = __float2bfloat16(x1);
    r0 = x0 - __bfloat162float(h0);
    r1 = x1 - __bfloat162float(h1);
    return ((uint32_t)__bfloat16_as_ushort(h1) << 16) | (uint32_t)__bfloat16_as_ushort(h0);
}
__device__ __forceinline__ uint32_t pack_bf(float x0, float x1) {
    __nv_bfloat16 h0 = __float2bfloat16(x0), h1 = __float2bfloat16(x1);
    return ((uint32_t)__bfloat16_as_ushort(h1) << 16) | (uint32_t)__bfloat16_as_ushort(h0);
}

// ---------------- kernel 0: tables + W split ----------------
__global__ void prep_kernel(const float* __restrict__ WQ,
                            const float* __restrict__ WK,
                            const float* __restrict__ WV) {
    int idx = blockIdx.x * blockDim.x + threadIdx.x;
    if (idx < 4096) {
        float d = fabsf((float)(idx - 2048));
        tDec[idx] = exp2f(log2f(0.96875f) * d);
    }
    if (idx < SEQ * 32) {
        int t = idx >> 5;
        int m = idx & 31;
        float sv = (2.0f * (float)m + 0.4f * (float)HD) / (1.4f * (float)HD);
        float s = powf(sv, (float)t / 512.0f);
        float invf = 1.0f / powf(10000.0f, (float)m / 32.0f);
        float ang = (float)t * invf;
        float sn, cs;
        sincosf(ang, &sn, &cs);
        tQc[idx] = cs * s;
        tQs[idx] = sn * s;
        tKc[idx] = cs / s;
        tKs[idx] = sn / s;
    }
    if (idx < 3 * HID * HD) {
        int region = idx >> 15;
        int k = (idx & 32767) >> 6;
        int d = idx & 63;
        const float* W = (region == 0) ? WQ : ((region == 1) ? WK : WV);
        float w = W[k * HD + d];
        __nv_bfloat16 hb = __float2bfloat16(w);
        gWh[(region * 64 + d) * HID + k] = __bfloat16_as_ushort(hb);
        gWl[(region * 64 + d) * HID + k] =
            __bfloat16_as_ushort(__float2bfloat16(w - __bfloat162float(hb)));
    }
}

// ---------------- kernel 1: QKV projection via HMMA + xPos ----------------
// 128 CTAs x 256 thr (8 warps 4x2). CTA tile 128x192, warp tile 32x96.
#define PSTR 72
#define P_AH 0
#define P_AL 18432
#define P_BH 36864
#define P_BL 64512
#define P_TOTAL 92160

__global__ __launch_bounds__(256, 1) void proj_kernel(const float* __restrict__ X) {
    extern __shared__ char sm[];
    uint16_t* Ah = (uint16_t*)(sm + P_AH);
    uint16_t* Al = (uint16_t*)(sm + P_AL);
    uint16_t* Bh = (uint16_t*)(sm + P_BH);
    uint16_t* Bl = (uint16_t*)(sm + P_BL);
    uint32_t smb = smem_u32(sm);

    int tid = threadIdx.x;
    int wid = tid >> 5, lane = tid & 31;
    int wm = wid >> 1, wn = wid & 1;
    int g = lane >> 2, tc = lane & 3;

    // per-thread ldmatrix address components
    int arow = lane & 15;                 // A-type (and also V-type) row offset
    int acolb = (lane >> 4) * 16;         // A-type col byte offset
    int krow = (lane & 7) + ((lane >> 4) << 3);   // B-type row offset
    int kcolb = ((lane >> 3) & 1) * 16;           // B-type col byte offset

    const float* Xb = X + (size_t)blockIdx.x * 128 * HID;

    float acc[2][12][4];
#pragma unroll
    for (int mt = 0; mt < 2; mt++)
#pragma unroll
        for (int nt = 0; nt < 12; nt++)
#pragma unroll
            for (int i = 0; i < 4; i++) acc[mt][nt][i] = 0.0f;

    for (int chunk = 0; chunk < 8; chunk++) {
        int k0 = chunk * 64;
        if (chunk) __syncthreads();
        // copy W slices (bf16, preconverted): 192 rows x 64 k
#pragma unroll
        for (int it = 0; it < 6; it++) {
            int e = tid + it * 256;
            int r = e >> 3, c = e & 7;
            *(float4*)&Bh[r * PSTR + c * 8] = *(const float4*)&gWh[r * HID + k0 + c * 8];
            *(float4*)&Bl[r * PSTR + c * 8] = *(const float4*)&gWl[r * HID + k0 + c * 8];
        }
        // convert A tile: 128 rows x 64 k
#pragma unroll
        for (int it = 0; it < 8; it++) {
            int e = tid + it * 256;
            int r = e >> 4, q = e & 15;
            float4 v = *(const float4*)&Xb[r * HID + k0 + 4 * q];
            float l0, l1, l2, l3;
            uint32_t h0 = cvt_hi(v.x, v.y, l0, l1);
            uint32_t h1 = cvt_hi(v.z, v.w, l2, l3);
            *(uint2*)&Ah[r * PSTR + 4 * q] = make_uint2(h0, h1);
            *(uint2*)&Al[r * PSTR + 4 * q] = make_uint2(pack_bf(l0, l1), pack_bf(l2, l3));
        }
        __syncthreads();

#pragma unroll
        for (int ks = 0; ks < 4; ks++) {
            uint32_t ah[2][4], al[2][4];
#pragma unroll
            for (int mt = 0; mt < 2; mt++) {
                uint32_t rb = (uint32_t)((wm * 32 + mt * 16 + arow) * (PSTR * 2) + ks * 32 + acolb);
                LDM_X4(ah[mt], smb + P_AH + rb);
                LDM_X4(al[mt], smb + P_AL + rb);
            }
#pragma unroll
            for (int np = 0; np < 6; np++) {
                int n = wn * 96 + np * 16;
                uint32_t bb = (uint32_t)((n + krow) * (PSTR * 2) + ks * 32 + kcolb);
                uint32_t bh[4], bl[4];
                LDM_X4(bh, smb + P_BH + bb);
                LDM_X4(bl, smb + P_BL + bb);
#pragma unroll
                for (int mt = 0; mt < 2; mt++) {
                    mma_bf16(acc[mt][2 * np], ah[mt], &bh[0]);
                    mma_bf16(acc[mt][2 * np], ah[mt], &bl[0]);
                    mma_bf16(acc[mt][2 * np], al[mt], &bh[0]);
                    mma_bf16(acc[mt][2 * np + 1], ah[mt], &bh[2]);
                    mma_bf16(acc[mt][2 * np + 1], ah[mt], &bl[2]);
                    mma_bf16(acc[mt][2 * np + 1], al[mt], &bh[2]);
                }
            }
        }
    }

    // epilogue: rotary on Q/K col pairs, split hi/lo, store
#pragma unroll
    for (int mt = 0; mt < 2; mt++) {
#pragma unroll
        for (int half = 0; half < 2; half++) {
            int lrow = wm * 32 + mt * 16 + g + half * 8;
            int grow = blockIdx.x * 128 + lrow;
            int tpos = grow & (SEQ - 1);
#pragma unroll
            for (int nt = 0; nt < 12; nt++) {
                int c = wn * 96 + nt * 8 + 2 * tc;
                float v0 = acc[mt][nt][half * 2];
                float v1 = acc[mt][nt][half * 2 + 1];
                if (c < 64) {
                    int m = c >> 1;
                    float cs = tQc[tpos * 32 + m], sn = tQs[tpos * 32 + m];
                    float o0 = v0 * cs - v1 * sn;
                    float o1 = v1 * cs + v0 * sn;
                    float l0, l1;
                    uint32_t hi = cvt_hi(o0, o1, l0, l1);
                    ((uint32_t*)gQh)[grow * 32 + m] = hi;
                    ((uint32_t*)gQl)[grow * 32 + m] = pack_bf(l0, l1);
                } else if (c < 128) {
                    int m = (c - 64) >> 1;
                    float cs = tKc[tpos * 32 + m], sn = tKs[tpos * 32 + m];
                    float o0 = v0 * cs - v1 * sn;
                    float o1 = v1 * cs + v0 * sn;
                    float l0, l1;
                    uint32_t hi = cvt_hi(o0, o1, l0, l1);
                    ((uint32_t*)gKh)[grow * 32 + m] = hi;
                    ((uint32_t*)gKl)[grow * 32 + m] = pack_bf(l0, l1);
                } else {
                    int m = (c - 128) >> 1;
                    float l0, l1;
                    uint32_t hi = cvt_hi(v0, v1, l0, l1);
                    ((uint32_t*)gVh)[grow * 32 + m] = hi;
                    ((uint32_t*)gVl)[grow * 32 + m] = pack_bf(l0, l1);
                }
            }
        }
    }
}

// ---------------- kernel 2: retention attention via HMMA (register S) ----------------
// grid (32 qt, 8 b) x 128 thr (4 warps). Warp = 16 rows x full 64 cols/dims.
#define ASTR 72
#define A_QH 0
#define A_QL 9216
#define A_KH 18432
#define A_KL 27648
#define A_VH 36864
#define A_VL 46080
#define A_TOTAL 55296

__global__ __launch_bounds__(128) void attn_kernel(float* __restrict__ out) {
    extern __shared__ char sm[];
    uint16_t* Qh = (uint16_t*)(sm + A_QH);
    uint16_t* Ql = (uint16_t*)(sm + A_QL);
    uint16_t* Kh = (uint16_t*)(sm + A_KH);
    uint16_t* Kl = (uint16_t*)(sm + A_KL);
    uint16_t* Vh = (uint16_t*)(sm + A_VH);
    uint16_t* Vl = (uint16_t*)(sm + A_VL);
    uint32_t smb = smem_u32(sm);

    int qt = 31 - blockIdx.x, b = blockIdx.y;
    int tid = threadIdx.x;
    int wid = tid >> 5, lane = tid & 31;
    int g = lane >> 2, tc = lane & 3;
    int q0 = qt * 64;
    int gb = b * SEQ + q0;

    int arow = lane & 15;
    int acolb = (lane >> 4) * 16;
    int krow = (lane & 7) + ((lane >> 4) << 3);
    int kcolb = ((lane >> 3) & 1) * 16;

    // load Q tile (hi/lo) once: 64 rows x 64 cols, 512 float4 per array
#pragma unroll
    for (int it = 0; it < 4; it++) {
        int e = tid + it * 128;
        int r = e >> 3, c = e & 7;
        *(float4*)&Qh[r * ASTR + c * 8] = *(const float4*)&gQh[(gb + r) * HD + c * 8];
        *(float4*)&Ql[r * ASTR + c * 8] = *(const float4*)&gQl[(gb + r) * HD + c * 8];
    }
    __syncthreads();

    // preload Q fragments
    uint32_t qh[4][4], ql[4][4];
#pragma unroll
    for (int ks = 0; ks < 4; ks++) {
        uint32_t rb = (uint32_t)((wid * 16 + arow) * (ASTR * 2) + ks * 32 + acolb);
        LDM_X4(qh[ks], smb + A_QH + rb);
        LDM_X4(ql[ks], smb + A_QL + rb);
    }

    float oa[8][4];
#pragma unroll
    for (int nd = 0; nd < 8; nd++)
#pragma unroll
        for (int i = 0; i < 4; i++) oa[nd][i] = 0.0f;

    int chunk = qt >> 2;
    int kt_end = (chunk + 1) * 4;
    int kt_start = qt - 8;
    if (kt_start < 0) kt_start = 0;
    int i0 = q0 + wid * 16 + g;

    for (int kt = kt_start; kt < kt_end; kt++) {
        __syncthreads();
        int kb = b * SEQ + kt * 64;
#pragma unroll
        for (int it = 0; it < 4; it++) {
            int e = tid + it * 128;
            int r = e >> 3, c = e & 7;
            *(float4*)&Kh[r * ASTR + c * 8] = *(const float4*)&gKh[(kb + r) * HD + c * 8];
            *(float4*)&Kl[r * ASTR + c * 8] = *(const float4*)&gKl[(kb + r) * HD + c * 8];
            *(float4*)&Vh[r * ASTR + c * 8] = *(const float4*)&gVh[(kb + r) * HD + c * 8];
            *(float4*)&Vl[r * ASTR + c * 8] = *(const float4*)&gVl[(kb + r) * HD + c * 8];
        }
        __syncthreads();

        // ---- S = Q K^T (warp tile 16x64) ----
        float s[8][4];
#pragma unroll
        for (int nt = 0; nt < 8; nt++)
#pragma unroll
            for (int i = 0; i < 4; i++) s[nt][i] = 0.0f;
#pragma unroll
        for (int ks = 0; ks < 4; ks++) {
#pragma unroll
            for (int np = 0; np < 4; np++) {
                uint32_t bb = (uint32_t)((np * 16 + krow) * (ASTR * 2) + ks * 32 + kcolb);
                uint32_t kh[4], kl[4];
                LDM_X4(kh, smb + A_KH + bb);
                LDM_X4(kl, smb + A_KL + bb);
                mma_bf16(s[2 * np], qh[ks], &kh[0]);
                mma_bf16(s[2 * np], qh[ks], &kl[0]);
                mma_bf16(s[2 * np], ql[ks], &kh[0]);
                mma_bf16(s[2 * np + 1], qh[ks], &kh[2]);
                mma_bf16(s[2 * np + 1], qh[ks], &kl[2]);
                mma_bf16(s[2 * np + 1], ql[ks], &kh[2]);
            }
        }

        // ---- decay (register) ----
#pragma unroll
        for (int nt = 0; nt < 8; nt++) {
            int jg = kt * 64 + nt * 8 + 2 * tc;
            s[nt][0] *= tDec[i0 - jg + 2048];
            s[nt][1] *= tDec[i0 - jg + 2047];
            s[nt][2] *= tDec[i0 + 8 - jg + 2048];
            s[nt][3] *= tDec[i0 + 8 - jg + 2047];
        }

        // ---- O += S V (S fragments straight from registers) ----
#pragma unroll
        for (int ks2 = 0; ks2 < 4; ks2++) {
            float* s0 = s[2 * ks2];
            float* s1 = s[2 * ks2 + 1];
            uint32_t ah[4], al[4];
            float l0, l1;
            ah[0] = cvt_hi(s0[0], s0[1], l0, l1); al[0] = pack_bf(l0, l1);
            ah[1] = cvt_hi(s0[2], s0[3], l0, l1); al[1] = pack_bf(l0, l1);
            ah[2] = cvt_hi(s1[0], s1[1], l0, l1); al[2] = pack_bf(l0, l1);
            ah[3] = cvt_hi(s1[2], s1[3], l0, l1); al[3] = pack_bf(l0, l1);
#pragma unroll
            for (int ndp = 0; ndp < 4; ndp++) {
                uint32_t vb = (uint32_t)((ks2 * 16 + arow) * (ASTR * 2) + ndp * 32 + acolb);
                uint32_t vh[4], vl[4];
                LDM_X4T(vh, smb + A_VH + vb);
                LDM_X4T(vl, smb + A_VL + vb);
                mma_bf16(oa[2 * ndp], ah, &vh[0]);
                mma_bf16(oa[2 * ndp], ah, &vl[0]);
                mma_bf16(oa[2 * ndp], al, &vh[0]);
                mma_bf16(oa[2 * ndp + 1], ah, &vh[2]);
                mma_bf16(oa[2 * ndp + 1], ah, &vl[2]);
                mma_bf16(oa[2 * ndp + 1], al, &vh[2]);
            }
        }
    }

    // store O
#pragma unroll
    for (int nd = 0; nd < 8; nd++) {
        int c = nd * 8 + 2 * tc;
        int r0 = wid * 16 + g;
        *(float2*)&out[(size_t)(gb + r0) * HD + c] = make_float2(oa[nd][0], oa[nd][1]);
        *(float2*)&out[(size_t)(gb + r0 + 8) * HD + c] = make_float2(oa[nd][2], oa[nd][3]);
    }
}

// ---------------- launch ----------------
extern "C" void kernel_launch(void* const* d_in, const int* in_sizes, int n_in,
                              void* d_out, int out_size) {
    const float* X  = (const float*)d_in[0];
    const float* WQ = (const float*)d_in[1];
    const float* WK = (const float*)d_in[2];
    const float* WV = (const float*)d_in[3];
    float* out = (float*)d_out;

    prep_kernel<<<384, 256>>>(WQ, WK, WV);

    cudaFuncSetAttribute(proj_kernel, cudaFuncAttributeMaxDynamicSharedMemorySize, P_TOTAL);
    proj_kernel<<<128, 256, P_TOTAL>>>(X);

    cudaFuncSetAttribute(attn_kernel, cudaFuncAttributeMaxDynamicSharedMemorySize, A_TOTAL);
    attn_kernel<<<dim3(32, B), 128, A_TOTAL>>>(out);
}

// round 5
// speedup vs baseline: 5.3205x; 1.0706x over previous
#include <cuda_runtime.h>
#include <cuda_bf16.h>
#include <math.h>
#include <stdint.h>

#define B 8
#define SEQ 2048
#define HID 512
#define HD 64

// ---------------- scratch (device globals; no allocation allowed) ----------------
__device__ __align__(256) uint16_t gQh[B * SEQ * HD], gQl[B * SEQ * HD];
__device__ __align__(256) uint16_t gKh[B * SEQ * HD], gKl[B * SEQ * HD];
__device__ __align__(256) uint16_t gVh[B * SEQ * HD], gVl[B * SEQ * HD];
__device__ __align__(256) uint16_t gWh[192 * HID], gWl[192 * HID];   // [region*64+d][k]
__device__ float tQc[SEQ * 32], tQs[SEQ * 32], tKc[SEQ * 32], tKs[SEQ * 32];
__device__ float tDec[4096];   // gamma^|d|, index d+2048

// ---------------- helpers ----------------
__device__ __forceinline__ void mma_bf16(float* d, const uint32_t* a, const uint32_t* b) {
    asm volatile(
        "mma.sync.aligned.m16n8k16.row.col.f32.bf16.bf16.f32 "
        "{%0,%1,%2,%3}, {%4,%5,%6,%7}, {%8,%9}, {%0,%1,%2,%3};"
        : "+f"(d[0]), "+f"(d[1]), "+f"(d[2]), "+f"(d[3])
        : "r"(a[0]), "r"(a[1]), "r"(a[2]), "r"(a[3]), "r"(b[0]), "r"(b[1]));
}
#define LDM_X4(R, a) \
    asm volatile("ldmatrix.sync.aligned.m8n8.x4.shared.b16 {%0,%1,%2,%3}, [%4];" \
                 : "=r"((R)[0]), "=r"((R)[1]), "=r"((R)[2]), "=r"((R)[3]) : "r"(a))
#define LDM_X4T(R, a) \
    asm volatile("ldmatrix.sync.aligned.m8n8.x4.trans.shared.b16 {%0,%1,%2,%3}, [%4];" \
                 : "=r"((R)[0]), "=r"((R)[1]), "=r"((R)[2]), "=r"((R)[3]) : "r"(a))
#define CPA16(dst, src) \
    asm volatile("cp.async.ca.shared.global [%0], [%1], 16;" \
                 :: "r"(dst), "l"(__cvta_generic_to_global(src)))
#define CPA_COMMIT() asm volatile("cp.async.commit_group;")
#define CPA_WAIT1() asm volatile("cp.async.wait_group 1;")
#define CPA_WAIT0() asm volatile("cp.async.wait_group 0;")
__device__ __forceinline__ uint32_t smem_u32(const void* p) {
    uint32_t a;
    asm("{ .reg .u64 t; cvta.to.shared.u64 t, %1; cvt.u32.u64 %0, t; }" : "=r"(a) : "l"(p));
    return a;
}
__device__ __forceinline__ uint32_t cvt_hi(float x0, float x1, float& r0, float& r1) {
    __nv_bfloat16 h0 = __float2bfloat16(x0), h1 = __float2bfloat16(x1);
    r0 = x0 - __bfloat162float(h0);
    r1 = x1 - __bfloat162float(h1);
    return ((uint32_t)__bfloat16_as_ushort(h1) << 16) | (uint32_t)__bfloat16_as_ushort(h0);
}
__device__ __forceinline__ uint32_t pack_bf(float x0, float x1) {
    __nv_bfloat16 h0 = __float2bfloat16(x0), h1 = __float2bfloat16(x1);
    return ((uint32_t)__bfloat16_as_ushort(h1) << 16) | (uint32_t)__bfloat16_as_ushort(h0);
}

// ---------------- kernel 0: tables + W split ----------------
__global__ void prep_kernel(const float* __restrict__ WQ,
                            const float* __restrict__ WK,
                            const float* __restrict__ WV) {
    int idx = blockIdx.x * blockDim.x + threadIdx.x;
    if (idx < 4096) {
        float d = fabsf((float)(idx - 2048));
        tDec[idx] = exp2f(log2f(0.96875f) * d);
    }
    if (idx < SEQ * 32) {
        int t = idx >> 5;
        int m = idx & 31;
        float sv = (2.0f * (float)m + 0.4f * (float)HD) / (1.4f * (float)HD);
        // scale: magnitude-only, exp2/log2 path is safe (1e-7 rel)
        float s = exp2f(((float)t * (1.0f / 512.0f)) * log2f(sv));
        // angle-critical: keep powf (matches prior measured 1.1e-5 baseline)
        float invf = 1.0f / powf(10000.0f, (float)m / 32.0f);
        float ang = (float)t * invf;
        float sn, cs;
        sincosf(ang, &sn, &cs);
        tQc[idx] = cs * s;
        tQs[idx] = sn * s;
        tKc[idx] = cs / s;
        tKs[idx] = sn / s;
    }
    if (idx < 3 * HID * HD) {
        int region = idx >> 15;
        int k = (idx & 32767) >> 6;
        int d = idx & 63;
        const float* W = (region == 0) ? WQ : ((region == 1) ? WK : WV);
        float w = W[k * HD + d];
        __nv_bfloat16 hb = __float2bfloat16(w);
        gWh[(region * 64 + d) * HID + k] = __bfloat16_as_ushort(hb);
        gWl[(region * 64 + d) * HID + k] =
            __bfloat16_as_ushort(__float2bfloat16(w - __bfloat162float(hb)));
    }
}

// ---------------- kernel 1: QKV projection via HMMA + xPos (cp.async pipelined) ----------------
// 128 CTAs x 256 thr (8 warps 4x2). CTA tile 128x192, warp tile 32x96.
#define PSTR 72
#define PX(s)   ((s) * 32768)                     // fp32 X staging, 128x64
#define P_BH(s) (65536 + (s) * 55296)             // bf16 W hi, 192x64 (stride 72)
#define P_BL(s) (65536 + (s) * 55296 + 27648)     // bf16 W lo
#define P_AH 176128
#define P_AL 194560
#define P_TOTAL 212992

__device__ __forceinline__ void proj_prefetch(uint32_t smb, const float* Xb, int k0,
                                              int s, int tid) {
#pragma unroll
    for (int it = 0; it < 8; it++) {
        int e = tid + it * 256;
        int r = e >> 4, c = e & 15;
        CPA16(smb + PX(s) + r * 256 + c * 16, &Xb[r * HID + k0 + c * 4]);
    }
#pragma unroll
    for (int it = 0; it < 6; it++) {
        int e = tid + it * 256;
        int r = e >> 3, c = e & 7;
        CPA16(smb + P_BH(s) + r * 144 + c * 16, &gWh[r * HID + k0 + c * 8]);
        CPA16(smb + P_BL(s) + r * 144 + c * 16, &gWl[r * HID + k0 + c * 8]);
    }
}

__global__ __launch_bounds__(256, 1) void proj_kernel(const float* __restrict__ X) {
    extern __shared__ char sm[];
    uint16_t* Ah = (uint16_t*)(sm + P_AH);
    uint16_t* Al = (uint16_t*)(sm + P_AL);
    uint32_t smb = smem_u32(sm);

    int tid = threadIdx.x;
    int wid = tid >> 5, lane = tid & 31;
    int wm = wid >> 1, wn = wid & 1;
    int g = lane >> 2, tc = lane & 3;

    int arow = lane & 15;
    int acolb = (lane >> 4) * 16;
    int krow = (lane & 7) + ((lane >> 4) << 3);
    int kcolb = ((lane >> 3) & 1) * 16;

    const float* Xb = X + (size_t)blockIdx.x * 128 * HID;

    float acc[2][12][4];
#pragma unroll
    for (int mt = 0; mt < 2; mt++)
#pragma unroll
        for (int nt = 0; nt < 12; nt++)
#pragma unroll
            for (int i = 0; i < 4; i++) acc[mt][nt][i] = 0.0f;

    proj_prefetch(smb, Xb, 0, 0, tid);
    CPA_COMMIT();

    for (int chunk = 0; chunk < 8; chunk++) {
        int s = chunk & 1;
        if (chunk < 7) {
            proj_prefetch(smb, Xb, (chunk + 1) * 64, s ^ 1, tid);
            CPA_COMMIT();
            CPA_WAIT1();
        } else {
            CPA_WAIT0();
        }
        __syncthreads();

        // convert staged fp32 X -> Ah/Al (bf16 hi/lo)
        {
            const float* Xs = (const float*)(sm + PX(s));
#pragma unroll
            for (int it = 0; it < 8; it++) {
                int e = tid + it * 256;
                int r = e >> 4, q = e & 15;
                float4 v = *(const float4*)&Xs[r * 64 + q * 4];
                float l0, l1, l2, l3;
                uint32_t h0 = cvt_hi(v.x, v.y, l0, l1);
                uint32_t h1 = cvt_hi(v.z, v.w, l2, l3);
                *(uint2*)&Ah[r * PSTR + 4 * q] = make_uint2(h0, h1);
                *(uint2*)&Al[r * PSTR + 4 * q] = make_uint2(pack_bf(l0, l1), pack_bf(l2, l3));
            }
        }
        __syncthreads();

        uint32_t bhBase = smb + P_BH(s);
        uint32_t blBase = smb + P_BL(s);
#pragma unroll
        for (int ks = 0; ks < 4; ks++) {
            uint32_t ah[2][4], al[2][4];
#pragma unroll
            for (int mt = 0; mt < 2; mt++) {
                uint32_t rb = (uint32_t)((wm * 32 + mt * 16 + arow) * (PSTR * 2) + ks * 32 + acolb);
                LDM_X4(ah[mt], smb + P_AH + rb);
                LDM_X4(al[mt], smb + P_AL + rb);
            }
#pragma unroll
            for (int np = 0; np < 6; np++) {
                int n = wn * 96 + np * 16;
                uint32_t bb = (uint32_t)((n + krow) * (PSTR * 2) + ks * 32 + kcolb);
                uint32_t bh[4], bl[4];
                LDM_X4(bh, bhBase + bb);
                LDM_X4(bl, blBase + bb);
#pragma unroll
                for (int mt = 0; mt < 2; mt++) {
                    mma_bf16(acc[mt][2 * np], ah[mt], &bh[0]);
                    mma_bf16(acc[mt][2 * np], ah[mt], &bl[0]);
                    mma_bf16(acc[mt][2 * np], al[mt], &bh[0]);
                    mma_bf16(acc[mt][2 * np + 1], ah[mt], &bh[2]);
                    mma_bf16(acc[mt][2 * np + 1], ah[mt], &bl[2]);
                    mma_bf16(acc[mt][2 * np + 1], al[mt], &bh[2]);
                }
            }
        }
        __syncthreads();
    }

    // epilogue: rotary on Q/K col pairs, split hi/lo, store
#pragma unroll
    for (int mt = 0; mt < 2; mt++) {
#pragma unroll
        for (int half = 0; half < 2; half++) {
            int lrow = wm * 32 + mt * 16 + g + half * 8;
            int grow = blockIdx.x * 128 + lrow;
            int tpos = grow & (SEQ - 1);
#pragma unroll
            for (int nt = 0; nt < 12; nt++) {
                int c = wn * 96 + nt * 8 + 2 * tc;
                float v0 = acc[mt][nt][half * 2];
                float v1 = acc[mt][nt][half * 2 + 1];
                if (c < 64) {
                    int m = c >> 1;
                    float cs = tQc[tpos * 32 + m], sn = tQs[tpos * 32 + m];
                    float o0 = v0 * cs - v1 * sn;
                    float o1 = v1 * cs + v0 * sn;
                    float l0, l1;
                    uint32_t hi = cvt_hi(o0, o1, l0, l1);
                    ((uint32_t*)gQh)[grow * 32 + m] = hi;
                    ((uint32_t*)gQl)[grow * 32 + m] = pack_bf(l0, l1);
                } else if (c < 128) {
                    int m = (c - 64) >> 1;
                    float cs = tKc[tpos * 32 + m], sn = tKs[tpos * 32 + m];
                    float o0 = v0 * cs - v1 * sn;
                    float o1 = v1 * cs + v0 * sn;
                    float l0, l1;
                    uint32_t hi = cvt_hi(o0, o1, l0, l1);
                    ((uint32_t*)gKh)[grow * 32 + m] = hi;
                    ((uint32_t*)gKl)[grow * 32 + m] = pack_bf(l0, l1);
                } else {
                    int m = (c - 128) >> 1;
                    float l0, l1;
                    uint32_t hi = cvt_hi(v0, v1, l0, l1);
                    ((uint32_t*)gVh)[grow * 32 + m] = hi;
                    ((uint32_t*)gVl)[grow * 32 + m] = pack_bf(l0, l1);
                }
            }
        }
    }
}

// ---------------- kernel 2: retention attention (pipelined, far-tile 1-term) ----------------
// grid (32 qt, 8 b) x 128 thr (4 warps). Warp = 16 rows x full 64 cols/dims.
#define ASTR 72
#define A_QH 0
#define A_QL 9216
#define A_ST 18432
#define A_STSZ 36864
// within stage: KH +0, KL +9216, VH +18432, VL +27648
#define A_TOTAL (A_ST + 2 * A_STSZ)   // 92160

__device__ __forceinline__ void attn_prefetch(uint32_t smb, int st, int kb, bool near_, int tid) {
    uint32_t base = smb + A_ST + st * A_STSZ;
#pragma unroll
    for (int it = 0; it < 4; it++) {
        int e = tid + it * 128;
        int r = e >> 3, c = e & 7;
        uint32_t off = (uint32_t)(r * 144 + c * 16);
        CPA16(base + off, &gKh[(size_t)(kb + r) * HD + c * 8]);
        CPA16(base + 18432 + off, &gVh[(size_t)(kb + r) * HD + c * 8]);
        if (near_) {
            CPA16(base + 9216 + off, &gKl[(size_t)(kb + r) * HD + c * 8]);
            CPA16(base + 27648 + off, &gVl[(size_t)(kb + r) * HD + c * 8]);
        }
    }
}

__global__ __launch_bounds__(128) void attn_kernel(float* __restrict__ out) {
    extern __shared__ char sm[];
    uint16_t* Qh = (uint16_t*)(sm + A_QH);
    uint16_t* Ql = (uint16_t*)(sm + A_QL);
    uint32_t smb = smem_u32(sm);

    int qt = 31 - blockIdx.x, b = blockIdx.y;
    int tid = threadIdx.x;
    int wid = tid >> 5, lane = tid & 31;
    int g = lane >> 2, tc = lane & 3;
    int q0 = qt * 64;
    int gb = b * SEQ + q0;

    int arow = lane & 15;
    int acolb = (lane >> 4) * 16;
    int krow = (lane & 7) + ((lane >> 4) << 3);
    int kcolb = ((lane >> 3) & 1) * 16;

    int chunk = qt >> 2;
    int kt_end = (chunk + 1) * 4;
    int kt_start = qt - 8;
    if (kt_start < 0) kt_start = 0;
    int n_tiles = kt_end - kt_start;

    // prefetch tile 0
    {
        int kt = kt_start;
        bool nr = (kt >= qt - 2) && (kt <= qt + 2);
        attn_prefetch(smb, 0, b * SEQ + kt * 64, nr, tid);
        CPA_COMMIT();
    }

    // load Q tile (hi/lo)
#pragma unroll
    for (int it = 0; it < 4; it++) {
        int e = tid + it * 128;
        int r = e >> 3, c = e & 7;
        *(float4*)&Qh[r * ASTR + c * 8] = *(const float4*)&gQh[(gb + r) * HD + c * 8];
        *(float4*)&Ql[r * ASTR + c * 8] = *(const float4*)&gQl[(gb + r) * HD + c * 8];
    }
    __syncthreads();

    // preload Q fragments
    uint32_t qh[4][4], ql[4][4];
#pragma unroll
    for (int ks = 0; ks < 4; ks++) {
        uint32_t rb = (uint32_t)((wid * 16 + arow) * (ASTR * 2) + ks * 32 + acolb);
        LDM_X4(qh[ks], smb + A_QH + rb);
        LDM_X4(ql[ks], smb + A_QL + rb);
    }

    float oa[8][4];
#pragma unroll
    for (int nd = 0; nd < 8; nd++)
#pragma unroll
        for (int i = 0; i < 4; i++) oa[nd][i] = 0.0f;

    int i0 = q0 + wid * 16 + g;

    for (int i = 0; i < n_tiles; i++) {
        int kt = kt_start + i;
        int s = i & 1;
        bool nr = (kt >= qt - 2) && (kt <= qt + 2);
        if (i + 1 < n_tiles) {
            int kt2 = kt + 1;
            bool nr2 = (kt2 >= qt - 2) && (kt2 <= qt + 2);
            attn_prefetch(smb, s ^ 1, b * SEQ + kt2 * 64, nr2, tid);
            CPA_COMMIT();
            CPA_WAIT1();
        } else {
            CPA_WAIT0();
        }
        __syncthreads();

        uint32_t stb = smb + A_ST + s * A_STSZ;
        uint32_t khB = stb, klB = stb + 9216, vhB = stb + 18432, vlB = stb + 27648;

        float sreg[8][4];
#pragma unroll
        for (int nt = 0; nt < 8; nt++)
#pragma unroll
            for (int ii = 0; ii < 4; ii++) sreg[nt][ii] = 0.0f;

        if (nr) {
            // ---- 3-term S = Q K^T ----
#pragma unroll
            for (int ks = 0; ks < 4; ks++) {
#pragma unroll
                for (int np = 0; np < 4; np++) {
                    uint32_t bb = (uint32_t)((np * 16 + krow) * (ASTR * 2) + ks * 32 + kcolb);
                    uint32_t kh[4], kl[4];
                    LDM_X4(kh, khB + bb);
                    LDM_X4(kl, klB + bb);
                    mma_bf16(sreg[2 * np], qh[ks], &kh[0]);
                    mma_bf16(sreg[2 * np], qh[ks], &kl[0]);
                    mma_bf16(sreg[2 * np], ql[ks], &kh[0]);
                    mma_bf16(sreg[2 * np + 1], qh[ks], &kh[2]);
                    mma_bf16(sreg[2 * np + 1], qh[ks], &kl[2]);
                    mma_bf16(sreg[2 * np + 1], ql[ks], &kh[2]);
                }
            }
            // ---- decay ----
#pragma unroll
            for (int nt = 0; nt < 8; nt++) {
                int jg = kt * 64 + nt * 8 + 2 * tc;
                sreg[nt][0] *= tDec[i0 - jg + 2048];
                sreg[nt][1] *= tDec[i0 - jg + 2047];
                sreg[nt][2] *= tDec[i0 + 8 - jg + 2048];
                sreg[nt][3] *= tDec[i0 + 8 - jg + 2047];
            }
            // ---- 3-term O += S V ----
#pragma unroll
            for (int ks2 = 0; ks2 < 4; ks2++) {
                float* s0 = sreg[2 * ks2];
                float* s1 = sreg[2 * ks2 + 1];
                uint32_t ah[4], al[4];
                float l0, l1;
                ah[0] = cvt_hi(s0[0], s0[1], l0, l1); al[0] = pack_bf(l0, l1);
                ah[1] = cvt_hi(s0[2], s0[3], l0, l1); al[1] = pack_bf(l0, l1);
                ah[2] = cvt_hi(s1[0], s1[1], l0, l1); al[2] = pack_bf(l0, l1);
                ah[3] = cvt_hi(s1[2], s1[3], l0, l1); al[3] = pack_bf(l0, l1);
#pragma unroll
                for (int ndp = 0; ndp < 4; ndp++) {
                    uint32_t vb = (uint32_t)((ks2 * 16 + arow) * (ASTR * 2) + ndp * 32 + acolb);
                    uint32_t vh[4], vl[4];
                    LDM_X4T(vh, vhB + vb);
                    LDM_X4T(vl, vlB + vb);
                    mma_bf16(oa[2 * ndp], ah, &vh[0]);
                    mma_bf16(oa[2 * ndp], ah, &vl[0]);
                    mma_bf16(oa[2 * ndp], al, &vh[0]);
                    mma_bf16(oa[2 * ndp + 1], ah, &vh[2]);
                    mma_bf16(oa[2 * ndp + 1], ah, &vl[2]);
                    mma_bf16(oa[2 * ndp + 1], al, &vh[2]);
                }
            }
        } else {
            // ---- far tile: decay <= gamma^129 = 0.017 -> 1-term bf16 ----
#pragma unroll
            for (int ks = 0; ks < 4; ks++) {
#pragma unroll
                for (int np = 0; np < 4; np++) {
                    uint32_t bb = (uint32_t)((np * 16 + krow) * (ASTR * 2) + ks * 32 + kcolb);
                    uint32_t kh[4];
                    LDM_X4(kh, khB + bb);
                    mma_bf16(sreg[2 * np], qh[ks], &kh[0]);
                    mma_bf16(sreg[2 * np + 1], qh[ks], &kh[2]);
                }
            }
#pragma unroll
            for (int nt = 0; nt < 8; nt++) {
                int jg = kt * 64 + nt * 8 + 2 * tc;
                sreg[nt][0] *= tDec[i0 - jg + 2048];
                sreg[nt][1] *= tDec[i0 - jg + 2047];
                sreg[nt][2] *= tDec[i0 + 8 - jg + 2048];
                sreg[nt][3] *= tDec[i0 + 8 - jg + 2047];
            }
#pragma unroll
            for (int ks2 = 0; ks2 < 4; ks2++) {
                float* s0 = sreg[2 * ks2];
                float* s1 = sreg[2 * ks2 + 1];
                uint32_t ah[4];
                ah[0] = pack_bf(s0[0], s0[1]);
                ah[1] = pack_bf(s0[2], s0[3]);
                ah[2] = pack_bf(s1[0], s1[1]);
                ah[3] = pack_bf(s1[2], s1[3]);
#pragma unroll
                for (int ndp = 0; ndp < 4; ndp++) {
                    uint32_t vb = (uint32_t)((ks2 * 16 + arow) * (ASTR * 2) + ndp * 32 + acolb);
                    uint32_t vh[4];
                    LDM_X4T(vh, vhB + vb);
                    mma_bf16(oa[2 * ndp], ah, &vh[0]);
                    mma_bf16(oa[2 * ndp + 1], ah, &vh[2]);
                }
            }
        }
        __syncthreads();
    }

    // store O
#pragma unroll
    for (int nd = 0; nd < 8; nd++) {
        int c = nd * 8 + 2 * tc;
        int r0 = wid * 16 + g;
        *(float2*)&out[(size_t)(gb + r0) * HD + c] = make_float2(oa[nd][0], oa[nd][1]);
        *(float2*)&out[(size_t)(gb + r0 + 8) * HD + c] = make_float2(oa[nd][2], oa[nd][3]);
    }
}

// ---------------- launch ----------------
extern "C" void kernel_launch(void* const* d_in, const int* in_sizes, int n_in,
                              void* d_out, int out_size) {
    const float* X  = (const float*)d_in[0];
    const float* WQ = (const float*)d_in[1];
    const float* WK = (const float*)d_in[2];
    const float* WV = (const float*)d_in[3];
    float* out = (float*)d_out;

    prep_kernel<<<384, 256>>>(WQ, WK, WV);

    cudaFuncSetAttribute(proj_kernel, cudaFuncAttributeMaxDynamicSharedMemorySize, P_TOTAL);
    proj_kernel<<<128, 256, P_TOTAL>>>(X);

    cudaFuncSetAttribute(attn_kernel, cudaFuncAttributeMaxDynamicSharedMemorySize, A_TOTAL);
    attn_kernel<<<dim3(32, B), 128, A_TOTAL>>>(out);
}

// round 6
// speedup vs baseline: 5.5314x; 1.0396x over previous
#include <cuda_runtime.h>
#include <cuda_bf16.h>
#include <math.h>
#include <stdint.h>

#define B 8
#define SEQ 2048
#define HID 512
#define HD 64

// ---------------- scratch (device globals; no allocation allowed) ----------------
__device__ __align__(256) uint16_t gQh[B * SEQ * HD], gQl[B * SEQ * HD];
__device__ __align__(256) uint16_t gKh[B * SEQ * HD], gKl[B * SEQ * HD];
__device__ __align__(256) uint16_t gVh[B * SEQ * HD], gVl[B * SEQ * HD];
__device__ __align__(256) uint16_t gWh[192 * HID], gWl[192 * HID];   // [region*64+d][k]
__device__ float tQc[SEQ * 32], tQs[SEQ * 32], tKc[SEQ * 32], tKs[SEQ * 32];
__device__ float tDec[4096];   // gamma^|d|, index d+2048

// ---------------- helpers ----------------
__device__ __forceinline__ void mma_bf16(float* d, const uint32_t* a, const uint32_t* b) {
    asm volatile(
        "mma.sync.aligned.m16n8k16.row.col.f32.bf16.bf16.f32 "
        "{%0,%1,%2,%3}, {%4,%5,%6,%7}, {%8,%9}, {%0,%1,%2,%3};"
        : "+f"(d[0]), "+f"(d[1]), "+f"(d[2]), "+f"(d[3])
        : "r"(a[0]), "r"(a[1]), "r"(a[2]), "r"(a[3]), "r"(b[0]), "r"(b[1]));
}
#define LDM_X4(R, a) \
    asm volatile("ldmatrix.sync.aligned.m8n8.x4.shared.b16 {%0,%1,%2,%3}, [%4];" \
                 : "=r"((R)[0]), "=r"((R)[1]), "=r"((R)[2]), "=r"((R)[3]) : "r"(a))
#define LDM_X4T(R, a) \
    asm volatile("ldmatrix.sync.aligned.m8n8.x4.trans.shared.b16 {%0,%1,%2,%3}, [%4];" \
                 : "=r"((R)[0]), "=r"((R)[1]), "=r"((R)[2]), "=r"((R)[3]) : "r"(a))
#define CPA16(dst, src) \
    asm volatile("cp.async.ca.shared.global [%0], [%1], 16;" \
                 :: "r"(dst), "l"(__cvta_generic_to_global(src)))
#define CPA_COMMIT() asm volatile("cp.async.commit_group;")
#define CPA_WAIT1() asm volatile("cp.async.wait_group 1;")
#define CPA_WAIT0() asm volatile("cp.async.wait_group 0;")
__device__ __forceinline__ uint32_t smem_u32(const void* p) {
    uint32_t a;
    asm("{ .reg .u64 t; cvta.to.shared.u64 t, %1; cvt.u32.u64 %0, t; }" : "=r"(a) : "l"(p));
    return a;
}
// fast bf16x2 pack (round-to-nearest): 1 instruction
__device__ __forceinline__ uint32_t pack_bf(float x0, float x1) {
    uint32_t r;
    asm("cvt.rn.bf16x2.f32 %0, %1, %2;" : "=r"(r) : "f"(x1), "f"(x0));
    return r;
}
// fast hi/lo split: hi = truncated bf16 pair (PRMT), lo = RN(residual) pair.
// hi + lo reconstructs x to ~2^-17 relative.
__device__ __forceinline__ uint32_t split_pair(float x0, float x1, uint32_t& lo) {
    uint32_t u0 = __float_as_uint(x0) & 0xFFFF0000u;
    uint32_t u1 = __float_as_uint(x1) & 0xFFFF0000u;
    uint32_t hi = __byte_perm(u0, u1, 0x7632);
    float l0 = x0 - __uint_as_float(u0);
    float l1 = x1 - __uint_as_float(u1);
    lo = pack_bf(l0, l1);
    return hi;
}

// ---------------- kernel 0: tables + W split ----------------
// grid 64 x 256 = 16384 threads. Per-m transcendentals hoisted out of the t loop.
__global__ void prep_kernel(const float* __restrict__ WQ,
                            const float* __restrict__ WK,
                            const float* __restrict__ WV) {
    int idx = blockIdx.x * blockDim.x + threadIdx.x;
    if (idx < 4096) {
        float d = fabsf((float)(idx - 2048));
        tDec[idx] = exp2f(log2f(0.96875f) * d);
    }
    if (idx < 8192) {
        int m = idx & 31;
        int t0 = (idx >> 5) * 8;
        float sv = (2.0f * (float)m + 0.4f * (float)HD) / (1.4f * (float)HD);
        float lsv = log2f(sv);
        // angle-critical base: keep powf (matches measured 2.2e-5 baseline)
        float invf = 1.0f / powf(10000.0f, (float)m / 32.0f);
#pragma unroll
        for (int dt = 0; dt < 8; dt++) {
            int t = t0 + dt;
            float s = exp2f(((float)t * (1.0f / 512.0f)) * lsv);
            float rs = 1.0f / s;
            float sn, cs;
            sincosf((float)t * invf, &sn, &cs);
            int o = t * 32 + m;
            tQc[o] = cs * s;
            tQs[o] = sn * s;
            tKc[o] = cs * rs;
            tKs[o] = sn * rs;
        }
    }
    // W split: 98304 elements, 6 per thread
    for (int e = idx; e < 3 * HID * HD; e += 16384) {
        int region = e >> 15;
        int k = (e & 32767) >> 6;
        int d = e & 63;
        const float* W = (region == 0) ? WQ : ((region == 1) ? WK : WV);
        float w = W[k * HD + d];
        __nv_bfloat16 hb = __float2bfloat16(w);
        gWh[(region * 64 + d) * HID + k] = __bfloat16_as_ushort(hb);
        gWl[(region * 64 + d) * HID + k] =
            __bfloat16_as_ushort(__float2bfloat16(w - __bfloat162float(hb)));
    }
}

// ---------------- kernel 1: QKV projection via HMMA + xPos (cp.async pipelined) ----------------
// 128 CTAs x 256 thr (8 warps 4x2). CTA tile 128x192, warp tile 32x96.
#define PSTR 72
#define PX(s)   ((s) * 32768)                     // fp32 X staging, 128x64
#define P_BH(s) (65536 + (s) * 55296)             // bf16 W hi, 192x64 (stride 72)
#define P_BL(s) (65536 + (s) * 55296 + 27648)     // bf16 W lo
#define P_AH 176128
#define P_AL 194560
#define P_TOTAL 212992

__device__ __forceinline__ void proj_prefetch(uint32_t smb, const float* Xb, int k0,
                                              int s, int tid) {
#pragma unroll
    for (int it = 0; it < 8; it++) {
        int e = tid + it * 256;
        int r = e >> 4, c = e & 15;
        CPA16(smb + PX(s) + r * 256 + c * 16, &Xb[r * HID + k0 + c * 4]);
    }
#pragma unroll
    for (int it = 0; it < 6; it++) {
        int e = tid + it * 256;
        int r = e >> 3, c = e & 7;
        CPA16(smb + P_BH(s) + r * 144 + c * 16, &gWh[r * HID + k0 + c * 8]);
        CPA16(smb + P_BL(s) + r * 144 + c * 16, &gWl[r * HID + k0 + c * 8]);
    }
}

__global__ __launch_bounds__(256, 1) void proj_kernel(const float* __restrict__ X) {
    extern __shared__ char sm[];
    uint16_t* Ah = (uint16_t*)(sm + P_AH);
    uint16_t* Al = (uint16_t*)(sm + P_AL);
    uint32_t smb = smem_u32(sm);

    int tid = threadIdx.x;
    int wid = tid >> 5, lane = tid & 31;
    int wm = wid >> 1, wn = wid & 1;
    int g = lane >> 2, tc = lane & 3;

    int arow = lane & 15;
    int acolb = (lane >> 4) * 16;
    int krow = (lane & 7) + ((lane >> 4) << 3);
    int kcolb = ((lane >> 3) & 1) * 16;

    const float* Xb = X + (size_t)blockIdx.x * 128 * HID;

    float acc[2][12][4];
#pragma unroll
    for (int mt = 0; mt < 2; mt++)
#pragma unroll
        for (int nt = 0; nt < 12; nt++)
#pragma unroll
            for (int i = 0; i < 4; i++) acc[mt][nt][i] = 0.0f;

    proj_prefetch(smb, Xb, 0, 0, tid);
    CPA_COMMIT();

    for (int chunk = 0; chunk < 8; chunk++) {
        int s = chunk & 1;
        if (chunk < 7) {
            proj_prefetch(smb, Xb, (chunk + 1) * 64, s ^ 1, tid);
            CPA_COMMIT();
            CPA_WAIT1();
        } else {
            CPA_WAIT0();
        }
        __syncthreads();

        // convert staged fp32 X -> Ah/Al (bf16 hi/lo) via PRMT split
        {
            const float* Xs = (const float*)(sm + PX(s));
#pragma unroll
            for (int it = 0; it < 8; it++) {
                int e = tid + it * 256;
                int r = e >> 4, q = e & 15;
                float4 v = *(const float4*)&Xs[r * 64 + q * 4];
                uint32_t lo0, lo1;
                uint32_t h0 = split_pair(v.x, v.y, lo0);
                uint32_t h1 = split_pair(v.z, v.w, lo1);
                *(uint2*)&Ah[r * PSTR + 4 * q] = make_uint2(h0, h1);
                *(uint2*)&Al[r * PSTR + 4 * q] = make_uint2(lo0, lo1);
            }
        }
        __syncthreads();

        uint32_t bhBase = smb + P_BH(s);
        uint32_t blBase = smb + P_BL(s);
#pragma unroll
        for (int ks = 0; ks < 4; ks++) {
            uint32_t ah[2][4], al[2][4];
#pragma unroll
            for (int mt = 0; mt < 2; mt++) {
                uint32_t rb = (uint32_t)((wm * 32 + mt * 16 + arow) * (PSTR * 2) + ks * 32 + acolb);
                LDM_X4(ah[mt], smb + P_AH + rb);
                LDM_X4(al[mt], smb + P_AL + rb);
            }
#pragma unroll
            for (int np = 0; np < 6; np++) {
                int n = wn * 96 + np * 16;
                uint32_t bb = (uint32_t)((n + krow) * (PSTR * 2) + ks * 32 + kcolb);
                uint32_t bh[4], bl[4];
                LDM_X4(bh, bhBase + bb);
                LDM_X4(bl, blBase + bb);
#pragma unroll
                for (int mt = 0; mt < 2; mt++) {
                    mma_bf16(acc[mt][2 * np], ah[mt], &bh[0]);
                    mma_bf16(acc[mt][2 * np], ah[mt], &bl[0]);
                    mma_bf16(acc[mt][2 * np], al[mt], &bh[0]);
                    mma_bf16(acc[mt][2 * np + 1], ah[mt], &bh[2]);
                    mma_bf16(acc[mt][2 * np + 1], ah[mt], &bl[2]);
                    mma_bf16(acc[mt][2 * np + 1], al[mt], &bh[2]);
                }
            }
        }
        __syncthreads();
    }

    // epilogue: rotary on Q/K col pairs, split hi/lo, store
#pragma unroll
    for (int mt = 0; mt < 2; mt++) {
#pragma unroll
        for (int half = 0; half < 2; half++) {
            int lrow = wm * 32 + mt * 16 + g + half * 8;
            int grow = blockIdx.x * 128 + lrow;
            int tpos = grow & (SEQ - 1);
#pragma unroll
            for (int nt = 0; nt < 12; nt++) {
                int c = wn * 96 + nt * 8 + 2 * tc;
                float v0 = acc[mt][nt][half * 2];
                float v1 = acc[mt][nt][half * 2 + 1];
                if (c < 64) {
                    int m = c >> 1;
                    float cs = tQc[tpos * 32 + m], sn = tQs[tpos * 32 + m];
                    float o0 = v0 * cs - v1 * sn;
                    float o1 = v1 * cs + v0 * sn;
                    uint32_t lo;
                    uint32_t hi = split_pair(o0, o1, lo);
                    ((uint32_t*)gQh)[grow * 32 + m] = hi;
                    ((uint32_t*)gQl)[grow * 32 + m] = lo;
                } else if (c < 128) {
                    int m = (c - 64) >> 1;
                    float cs = tKc[tpos * 32 + m], sn = tKs[tpos * 32 + m];
                    float o0 = v0 * cs - v1 * sn;
                    float o1 = v1 * cs + v0 * sn;
                    uint32_t lo;
                    uint32_t hi = split_pair(o0, o1, lo);
                    ((uint32_t*)gKh)[grow * 32 + m] = hi;
                    ((uint32_t*)gKl)[grow * 32 + m] = lo;
                } else {
                    int m = (c - 128) >> 1;
                    uint32_t lo;
                    uint32_t hi = split_pair(v0, v1, lo);
                    ((uint32_t*)gVh)[grow * 32 + m] = hi;
                    ((uint32_t*)gVl)[grow * 32 + m] = lo;
                }
            }
        }
    }
}

// ---------------- kernel 2: retention attention (pipelined, far-tile 1-term) ----------------
// grid (32 qt, 8 b) x 128 thr (4 warps). Warp = 16 rows x full 64 cols/dims.
#define ASTR 72
#define A_QH 0
#define A_QL 9216
#define A_ST 18432
#define A_STSZ 36864
// within stage: KH +0, KL +9216, VH +18432, VL +27648
#define A_DEC (A_ST + 2 * A_STSZ)            // 92160: decay window, 832 floats
#define A_TOTAL (A_DEC + 832 * 4)            // 95488

__device__ __forceinline__ void attn_prefetch(uint32_t smb, int st, int kb, bool near_, int tid) {
    uint32_t base = smb + A_ST + st * A_STSZ;
#pragma unroll
    for (int it = 0; it < 4; it++) {
        int e = tid + it * 128;
        int r = e >> 3, c = e & 7;
        uint32_t off = (uint32_t)(r * 144 + c * 16);
        CPA16(base + off, &gKh[(size_t)(kb + r) * HD + c * 8]);
        CPA16(base + 18432 + off, &gVh[(size_t)(kb + r) * HD + c * 8]);
        if (near_) {
            CPA16(base + 9216 + off, &gKl[(size_t)(kb + r) * HD + c * 8]);
            CPA16(base + 27648 + off, &gVl[(size_t)(kb + r) * HD + c * 8]);
        }
    }
}

__global__ __launch_bounds__(128) void attn_kernel(float* __restrict__ out) {
    extern __shared__ char sm[];
    uint16_t* Qh = (uint16_t*)(sm + A_QH);
    uint16_t* Ql = (uint16_t*)(sm + A_QL);
    float* sDec = (float*)(sm + A_DEC);
    uint32_t smb = smem_u32(sm);

    int qt = 31 - blockIdx.x, b = blockIdx.y;
    int tid = threadIdx.x;
    int wid = tid >> 5, lane = tid & 31;
    int g = lane >> 2, tc = lane & 3;
    int q0 = qt * 64;
    int gb = b * SEQ + q0;

    int arow = lane & 15;
    int acolb = (lane >> 4) * 16;
    int krow = (lane & 7) + ((lane >> 4) << 3);
    int kcolb = ((lane >> 3) & 1) * 16;

    int chunk = qt >> 2;
    int kt_end = (chunk + 1) * 4;
    int kt_start = qt - 8;
    if (kt_start < 0) kt_start = 0;
    int n_tiles = kt_end - kt_start;

    // prefetch tile 0
    {
        int kt = kt_start;
        bool nr = (kt >= qt - 2) && (kt <= qt + 2);
        attn_prefetch(smb, 0, b * SEQ + kt * 64, nr, tid);
        CPA_COMMIT();
    }

    // load Q tile (hi/lo) + decay window (delta = i-j in [-255, 575] -> sDec[delta+255])
#pragma unroll
    for (int it = 0; it < 4; it++) {
        int e = tid + it * 128;
        int r = e >> 3, c = e & 7;
        *(float4*)&Qh[r * ASTR + c * 8] = *(const float4*)&gQh[(gb + r) * HD + c * 8];
        *(float4*)&Ql[r * ASTR + c * 8] = *(const float4*)&gQl[(gb + r) * HD + c * 8];
    }
    for (int d = tid; d < 832; d += 128) sDec[d] = tDec[d + 1793];
    __syncthreads();

    // preload Q fragments
    uint32_t qh[4][4], ql[4][4];
#pragma unroll
    for (int ks = 0; ks < 4; ks++) {
        uint32_t rb = (uint32_t)((wid * 16 + arow) * (ASTR * 2) + ks * 32 + acolb);
        LDM_X4(qh[ks], smb + A_QH + rb);
        LDM_X4(ql[ks], smb + A_QL + rb);
    }

    float oa[8][4];
#pragma unroll
    for (int nd = 0; nd < 8; nd++)
#pragma unroll
        for (int i = 0; i < 4; i++) oa[nd][i] = 0.0f;

    int i0 = q0 + wid * 16 + g;

    for (int i = 0; i < n_tiles; i++) {
        int kt = kt_start + i;
        int s = i & 1;
        bool nr = (kt >= qt - 2) && (kt <= qt + 2);
        if (i + 1 < n_tiles) {
            int kt2 = kt + 1;
            bool nr2 = (kt2 >= qt - 2) && (kt2 <= qt + 2);
            attn_prefetch(smb, s ^ 1, b * SEQ + kt2 * 64, nr2, tid);
            CPA_COMMIT();
            CPA_WAIT1();
        } else {
            CPA_WAIT0();
        }
        __syncthreads();

        uint32_t stb = smb + A_ST + s * A_STSZ;
        uint32_t khB = stb, klB = stb + 9216, vhB = stb + 18432, vlB = stb + 27648;

        float sreg[8][4];
#pragma unroll
        for (int nt = 0; nt < 8; nt++)
#pragma unroll
            for (int ii = 0; ii < 4; ii++) sreg[nt][ii] = 0.0f;

        if (nr) {
            // ---- 3-term S = Q K^T ----
#pragma unroll
            for (int ks = 0; ks < 4; ks++) {
#pragma unroll
                for (int np = 0; np < 4; np++) {
                    uint32_t bb = (uint32_t)((np * 16 + krow) * (ASTR * 2) + ks * 32 + kcolb);
                    uint32_t kh[4], kl[4];
                    LDM_X4(kh, khB + bb);
                    LDM_X4(kl, klB + bb);
                    mma_bf16(sreg[2 * np], qh[ks], &kh[0]);
                    mma_bf16(sreg[2 * np], qh[ks], &kl[0]);
                    mma_bf16(sreg[2 * np], ql[ks], &kh[0]);
                    mma_bf16(sreg[2 * np + 1], qh[ks], &kh[2]);
                    mma_bf16(sreg[2 * np + 1], qh[ks], &kl[2]);
                    mma_bf16(sreg[2 * np + 1], ql[ks], &kh[2]);
                }
            }
            // ---- decay (smem window) ----
#pragma unroll
            for (int nt = 0; nt < 8; nt++) {
                int base = i0 - (kt * 64 + nt * 8 + 2 * tc) + 255;
                sreg[nt][0] *= sDec[base];
                sreg[nt][1] *= sDec[base - 1];
                sreg[nt][2] *= sDec[base + 8];
                sreg[nt][3] *= sDec[base + 7];
            }
            // ---- 3-term O += S V ----
#pragma unroll
            for (int ks2 = 0; ks2 < 4; ks2++) {
                float* s0 = sreg[2 * ks2];
                float* s1 = sreg[2 * ks2 + 1];
                uint32_t ah[4], al[4];
                ah[0] = split_pair(s0[0], s0[1], al[0]);
                ah[1] = split_pair(s0[2], s0[3], al[1]);
                ah[2] = split_pair(s1[0], s1[1], al[2]);
                ah[3] = split_pair(s1[2], s1[3], al[3]);
#pragma unroll
                for (int ndp = 0; ndp < 4; ndp++) {
                    uint32_t vb = (uint32_t)((ks2 * 16 + arow) * (ASTR * 2) + ndp * 32 + acolb);
                    uint32_t vh[4], vl[4];
                    LDM_X4T(vh, vhB + vb);
                    LDM_X4T(vl, vlB + vb);
                    mma_bf16(oa[2 * ndp], ah, &vh[0]);
                    mma_bf16(oa[2 * ndp], ah, &vl[0]);
                    mma_bf16(oa[2 * ndp], al, &vh[0]);
                    mma_bf16(oa[2 * ndp + 1], ah, &vh[2]);
                    mma_bf16(oa[2 * ndp + 1], ah, &vl[2]);
                    mma_bf16(oa[2 * ndp + 1], al, &vh[2]);
                }
            }
        } else {
            // ---- far tile: decay <= gamma^129 = 0.017 -> 1-term bf16 ----
#pragma unroll
            for (int ks = 0; ks < 4; ks++) {
#pragma unroll
                for (int np = 0; np < 4; np++) {
                    uint32_t bb = (uint32_t)((np * 16 + krow) * (ASTR * 2) + ks * 32 + kcolb);
                    uint32_t kh[4];
                    LDM_X4(kh, khB + bb);
                    mma_bf16(sreg[2 * np], qh[ks], &kh[0]);
                    mma_bf16(sreg[2 * np + 1], qh[ks], &kh[2]);
                }
            }
#pragma unroll
            for (int nt = 0; nt < 8; nt++) {
                int base = i0 - (kt * 64 + nt * 8 + 2 * tc) + 255;
                sreg[nt][0] *= sDec[base];
                sreg[nt][1] *= sDec[base - 1];
                sreg[nt][2] *= sDec[base + 8];
                sreg[nt][3] *= sDec[base + 7];
            }
#pragma unroll
            for (int ks2 = 0; ks2 < 4; ks2++) {
                float* s0 = sreg[2 * ks2];
                float* s1 = sreg[2 * ks2 + 1];
                uint32_t ah[4];
                ah[0] = pack_bf(s0[0], s0[1]);
                ah[1] = pack_bf(s0[2], s0[3]);
                ah[2] = pack_bf(s1[0], s1[1]);
                ah[3] = pack_bf(s1[2], s1[3]);
#pragma unroll
                for (int ndp = 0; ndp < 4; ndp++) {
                    uint32_t vb = (uint32_t)((ks2 * 16 + arow) * (ASTR * 2) + ndp * 32 + acolb);
                    uint32_t vh[4];
                    LDM_X4T(vh, vhB + vb);
                    mma_bf16(oa[2 * ndp], ah, &vh[0]);
                    mma_bf16(oa[2 * ndp + 1], ah, &vh[2]);
                }
            }
        }
        __syncthreads();
    }

    // store O
#pragma unroll
    for (int nd = 0; nd < 8; nd++) {
        int c = nd * 8 + 2 * tc;
        int r0 = wid * 16 + g;
        *(float2*)&out[(size_t)(gb + r0) * HD + c] = make_float2(oa[nd][0], oa[nd][1]);
        *(float2*)&out[(size_t)(gb + r0 + 8) * HD + c] = make_float2(oa[nd][2], oa[nd][3]);
    }
}

// ---------------- launch ----------------
extern "C" void kernel_launch(void* const* d_in, const int* in_sizes, int n_in,
                              void* d_out, int out_size) {
    const float* X  = (const float*)d_in[0];
    const float* WQ = (const float*)d_in[1];
    const float* WK = (const float*)d_in[2];
    const float* WV = (const float*)d_in[3];
    float* out = (float*)d_out;

    prep_kernel<<<64, 256>>>(WQ, WK, WV);

    cudaFuncSetAttribute(proj_kernel, cudaFuncAttributeMaxDynamicSharedMemorySize, P_TOTAL);
    proj_kernel<<<128, 256, P_TOTAL>>>(X);

    cudaFuncSetAttribute(attn_kernel, cudaFuncAttributeMaxDynamicSharedMemorySize, A_TOTAL);
    attn_kernel<<<dim3(32, B), 128, A_TOTAL>>>(out);
}